// round 7
// baseline (speedup 1.0000x reference)
#include <cuda_runtime.h>
#include <cuda_fp16.h>
#include <cuda_bf16.h>

#define WAY   5
#define NQ    75
#define CIN   640
#define NTOK  512
#define CP    64
#define PAIRS (WAY*NQ)          /* 375 */
#define BN_EPS 1e-5f
#define GN_EPS 1e-5f
#define L2_EPS 1e-8f
#define LOG2E  1.4426950408889634f

/* scratch (device globals)
 * g_S/g_Q: [batch][tok 512][ch 64], channels PERMUTED by perm8() */
__device__ float g_S[WAY*NTOK*CP];
__device__ float g_Q[NQ*NTOK*CP];
__device__ float g_mS[WAY*NTOK];
__device__ float g_mQ[NQ*NTOK];
__device__ float g_G[(WAY+NQ)*CP*CP];     // centered Gram per batch (permuted basis)
__device__ float g_bar[(WAY+NQ)*CP];      // token-mean vector per batch (permuted)
__device__ float g_as[PAIRS*NTOK];
__device__ float g_aq[PAIRS*NTOK];
__device__ float g_wsum[CP];
__device__ float g_scale[CP];
__device__ float g_bias[CP];

__device__ __forceinline__ float ex2(float x) {
    float y;
    asm("ex2.approx.ftz.f32 %0, %1;" : "=f"(y) : "f"(x));
    return y;
}
__device__ __forceinline__ float warp_sum(float v) {
    #pragma unroll
    for (int o = 16; o; o >>= 1) v += __shfl_xor_sync(0xffffffffu, v, o);
    return v;
}
__device__ __forceinline__ unsigned to_tf32(float f) {
    unsigned u;
    asm("cvt.rna.tf32.f32 %0, %1;" : "=r"(u) : "f"(f));
    return u;
}
__device__ __forceinline__ int perm8(int c) {
    return (c & ~7) | ((c & 3) * 2) | ((c >> 2) & 1);
}
__device__ __forceinline__ void mma_tf32(float* d, unsigned a0, unsigned a1,
                                         unsigned a2, unsigned a3,
                                         unsigned b0, unsigned b1) {
    asm volatile(
        "mma.sync.aligned.m16n8k8.row.col.f32.tf32.tf32.f32 "
        "{%0,%1,%2,%3}, {%4,%5,%6,%7}, {%8,%9}, {%0,%1,%2,%3};"
        : "+f"(d[0]), "+f"(d[1]), "+f"(d[2]), "+f"(d[3])
        : "r"(a0), "r"(a1), "r"(a2), "r"(a3), "r"(b0), "r"(b1));
}

/* ------------- K-pre: BN fold + weight row sums (parallel) ------------- */
__global__ void kpre(const float* __restrict__ W, const float* __restrict__ gamma,
                     const float* __restrict__ beta, const float* __restrict__ mean,
                     const float* __restrict__ var) {
    int t = threadIdx.x;            // 256 threads
    int o = t >> 2, ln = t & 3;
    float s = 0.f;
    for (int c = ln; c < CIN; c += 4) s += W[o*CIN + c];
    s += __shfl_xor_sync(0xffffffffu, s, 1);
    s += __shfl_xor_sync(0xffffffffu, s, 2);
    if (ln == 0) {
        g_wsum[o] = s;
        float sc = gamma[o] * rsqrtf(var[o] + BN_EPS);
        g_scale[o] = sc;
        g_bias[o]  = beta[o] - mean[o] * sc;
    }
}

/* ------------- K0: projection, writes transposed+permuted [tok][64] ------------- */
__global__ __launch_bounds__(256) void kproj(const float* __restrict__ sup,
                                             const float* __restrict__ qry,
                                             const float* __restrict__ W) {
    __shared__ float pool[128*68];
    __shared__ float minv[128];
    __shared__ float linv[128];
    float* ws = pool;                  // [32][65]
    float* xs = pool + 32*65;          // [32][128]

    int b  = blockIdx.x >> 2;
    int n0 = (blockIdx.x & 3) * 128;
    const float* x  = (b < WAY) ? sup + (size_t)b*CIN*NTOK : qry + (size_t)(b-WAY)*CIN*NTOK;
    float* outp     = (b < WAY) ? g_S + b*NTOK*CP          : g_Q + (b-WAY)*NTOK*CP;
    float* moutp    = (b < WAY) ? g_mS + b*NTOK            : g_mQ + (b-WAY)*NTOK;

    int t  = threadIdx.x;
    int tx = t & 15, ty = t >> 4;

    float acc[4][8];
    #pragma unroll
    for (int u = 0; u < 4; u++)
        #pragma unroll
        for (int v = 0; v < 8; v++) acc[u][v] = 0.f;
    float cs = 0.f;

    for (int cc = 0; cc < CIN; cc += 32) {
        for (int j = t; j < 32*64; j += 256) {
            int o = j >> 5, cr = j & 31;
            ws[cr*65 + o] = W[o*CIN + cc + cr];
        }
        for (int j = t; j < 32*128; j += 256) {
            int r = j >> 7, col = j & 127;
            xs[r*128 + col] = x[(size_t)(cc + r)*NTOK + n0 + col];
        }
        __syncthreads();
        if (t < 128) {
            #pragma unroll 8
            for (int r = 0; r < 32; r++) cs += xs[r*128 + t];
        }
        #pragma unroll 4
        for (int kc = 0; kc < 32; kc++) {
            float a[4], bb[8];
            #pragma unroll
            for (int u = 0; u < 4; u++) a[u] = ws[kc*65 + ty*4 + u];
            #pragma unroll
            for (int v = 0; v < 8; v++) bb[v] = xs[kc*128 + tx*8 + v];
            #pragma unroll
            for (int u = 0; u < 4; u++)
                #pragma unroll
                for (int v = 0; v < 8; v++)
                    acc[u][v] = fmaf(a[u], bb[v], acc[u][v]);
        }
        __syncthreads();
    }
    if (t < 128) minv[t] = cs * (1.f/CIN);
    __syncthreads();

    float* psum = pool;
    float ssq[8];
    #pragma unroll
    for (int v = 0; v < 8; v++) ssq[v] = 0.f;
    #pragma unroll
    for (int u = 0; u < 4; u++) {
        int o = ty*4 + u;
        float wsm = g_wsum[o], sc = g_scale[o], bi = g_bias[o];
        #pragma unroll
        for (int v = 0; v < 8; v++) {
            float y = acc[u][v] - wsm * minv[tx*8 + v];
            y = fmaxf(y * sc + bi, 0.f);
            acc[u][v] = y;
            ssq[v] += y * y;
        }
    }
    #pragma unroll
    for (int v = 0; v < 8; v++) psum[ty*128 + tx*8 + v] = ssq[v];
    __syncthreads();
    if (t < 128) {
        float s = 0.f;
        #pragma unroll
        for (int r = 0; r < 16; r++) s += psum[r*128 + t];
        linv[t] = 1.f / fmaxf(sqrtf(s), L2_EPS);
        moutp[n0 + t] = minv[t];
    }
    __syncthreads();

    float* stg = pool;                 // [128][68]
    #pragma unroll
    for (int u = 0; u < 4; u++) {
        int p = perm8(ty*4 + u);
        #pragma unroll
        for (int v = 0; v < 8; v++) {
            int col = tx*8 + v;
            stg[col*68 + p] = acc[u][v] * linv[col];
        }
    }
    __syncthreads();
    for (int idx = t; idx < 128*16; idx += 256) {
        int col = idx >> 4, c4 = (idx & 15) << 2;
        float4 val = *(float4*)&stg[col*68 + c4];
        *(float4*)(outp + (size_t)(n0 + col)*CP + c4) = val;
    }
}

/* ------------- Kgram: per batch token-mean + centered Gram (64x64) ------------- */
__global__ __launch_bounds__(256) void kgram() {
    __shared__ float Xs[128*68];
    __shared__ float abar_s[64];

    int b = blockIdx.x;
    const float* X = (b < WAY) ? g_S + (size_t)b*NTOK*CP
                               : g_Q + (size_t)(b-WAY)*NTOK*CP;
    int t = threadIdx.x;

    float csum = 0.f;
    for (int ck = 0; ck < 4; ck++) {
        for (int idx = t; idx < 128*16; idx += 256) {
            int r = idx >> 4, c4 = (idx & 15) << 2;
            *(float4*)&Xs[r*68 + c4] = *(const float4*)(X + (size_t)(ck*128 + r)*CP + c4);
        }
        __syncthreads();
        if (t < 64) {
            #pragma unroll 8
            for (int r = 0; r < 128; r++) csum += Xs[r*68 + t];
        }
        __syncthreads();
    }
    if (t < 64) {
        float m = csum * (1.f/512.f);
        abar_s[t] = m;
        g_bar[b*CP + t] = m;
    }
    __syncthreads();

    float gacc[4][4];
    #pragma unroll
    for (int i = 0; i < 4; i++)
        #pragma unroll
        for (int j = 0; j < 4; j++) gacc[i][j] = 0.f;
    int a0 = (t >> 4) * 4, b0 = (t & 15) * 4;

    for (int ck = 0; ck < 4; ck++) {
        for (int idx = t; idx < 128*16; idx += 256) {
            int r = idx >> 4, c4 = (idx & 15) << 2;
            float4 v = *(const float4*)(X + (size_t)(ck*128 + r)*CP + c4);
            v.x -= abar_s[c4+0]; v.y -= abar_s[c4+1];
            v.z -= abar_s[c4+2]; v.w -= abar_s[c4+3];
            *(float4*)&Xs[r*68 + c4] = v;
        }
        __syncthreads();
        #pragma unroll 4
        for (int r = 0; r < 128; r++) {
            float4 av = *(float4*)&Xs[r*68 + a0];
            float4 bv = *(float4*)&Xs[r*68 + b0];
            float aa[4] = {av.x, av.y, av.z, av.w};
            float bb[4] = {bv.x, bv.y, bv.z, bv.w};
            #pragma unroll
            for (int i = 0; i < 4; i++)
                #pragma unroll
                for (int j = 0; j < 4; j++)
                    gacc[i][j] = fmaf(aa[i], bb[j], gacc[i][j]);
        }
        __syncthreads();
    }
    #pragma unroll
    for (int i = 0; i < 4; i++)
        #pragma unroll
        for (int j = 0; j < 4; j++)
            g_G[(size_t)b*CP*CP + (a0+i)*CP + b0+j] = gacc[i][j];
}

/* ------------- Kpass: fused storeless GEMM + gaussian-softmax + attn sums -------------
 * 64-col B stripes x 64-row A blocks; 2 CTAs/SM (108.5 KB smem, <=128 regs).
 * Per stripe: stage B + Gram (Gram aliased into Ebuf head), stats via H=B*G' mma,
 * 8 A blocks of tf32 GEMM -> exp -> Ebuf fp16 (stride 70: conflict-free attn read),
 * Z partials in regs across blocks, one reduce, then attn row sums from Ebuf.
 */
#define KP_SMEM_BYTES ((64*68 + 64*68)*4 + 512*70*2 + (64*5 + 64*3)*4)   /* 108544 */

extern "C" __global__ void __launch_bounds__(256, 2) kpass() {
    extern __shared__ unsigned char kp_sm[];
    unsigned* Bstf = (unsigned*)kp_sm;              // [64][68] tf32
    unsigned* Astf = Bstf + 64*68;                  // [64][68]
    __half*  Ebuf  = (__half*)(Astf + 64*68);       // [512][70]
    unsigned* Gm   = (unsigned*)Ebuf;               // alias: [64][68] tf32 (+abar bits at col 64)
    float* zred    = (float*)(Ebuf + 512*70);       // [64][5]
    float* bscale  = zred + 64*5;                   // [64]
    float* bofs    = bscale + 64;                   // [64]
    float* zsum    = bofs + 64;                     // [64]

    int bid = blockIdx.x;
    int mode = (bid >= PAIRS);
    int pair = bid - mode*PAIRS;
    int qq = pair / WAY, ww = pair % WAY;
    const float *A, *B, *Gp, *barp;
    float* outp;
    if (mode == 0) {
        A = g_S + (size_t)ww*NTOK*CP;  B = g_Q + (size_t)qq*NTOK*CP;
        Gp = g_G + (size_t)ww*CP*CP;   barp = g_bar + ww*CP;
        outp = g_as + pair*NTOK;
    } else {
        A = g_Q + (size_t)qq*NTOK*CP;  B = g_S + (size_t)ww*NTOK*CP;
        Gp = g_G + (size_t)(WAY+qq)*CP*CP;  barp = g_bar + (WAY+qq)*CP;
        outp = g_aq + pair*NTOK;
    }

    int t = threadIdx.x, lane = t & 31, warp = t >> 5;
    int wi = warp >> 1, wj = warp & 1;
    int la = lane >> 2, lb = lane & 3;

    int srow = t >> 4;            // staging row base (0..15)
    int scol = (t & 15) << 2;     // staging col (0,4,..,60)

    float attn0 = 0.f, attn1 = 0.f;

    for (int sb = 0; sb < 8; sb++) {
        __syncthreads();   /* Ebuf consumed by prior attn phase; Bstf free */

        /* stage B stripe [64 rows][64 ch] + Gram + abar */
        #pragma unroll
        for (int j = 0; j < 4; j++) {
            int r = srow + j*16;
            float4 v = *(const float4*)(B + (size_t)(sb*64 + r)*CP + scol);
            *(uint4*)(Bstf + r*68 + scol) =
                make_uint4(to_tf32(v.x), to_tf32(v.y), to_tf32(v.z), to_tf32(v.w));
        }
        #pragma unroll
        for (int j = 0; j < 4; j++) {
            int r = srow + j*16;
            float4 v = *(const float4*)(Gp + r*CP + scol);
            *(uint4*)(Gm + r*68 + scol) =
                make_uint4(to_tf32(v.x), to_tf32(v.y), to_tf32(v.z), to_tf32(v.w));
        }
        if (t < 64) Gm[t*68 + 64] = __float_as_uint(barp[t]);
        __syncthreads();

        /* stats: H = B * G'; 511*var_j = b_j . h_j ; mean_j = abar . b_j */
        {
            float sacc[4][4];
            #pragma unroll
            for (int n = 0; n < 4; n++)
                #pragma unroll
                for (int e = 0; e < 4; e++) sacc[n][e] = 0.f;
            #pragma unroll
            for (int ks = 0; ks < 8; ks++) {
                int k0 = ks*8 + 2*lb;
                uint2 a0 = *(uint2*)(Bstf + (wi*16 + la)*68 + k0);
                uint2 a1 = *(uint2*)(Bstf + (wi*16 + la + 8)*68 + k0);
                uint2 bf[4];
                #pragma unroll
                for (int n = 0; n < 4; n++)
                    bf[n] = *(uint2*)(Gm + (wj*32 + n*8 + la)*68 + k0);
                #pragma unroll
                for (int n = 0; n < 4; n++)
                    mma_tf32(sacc[n], a0.x, a1.x, a0.y, a1.y, bf[n].x, bf[n].y);
            }
            #pragma unroll
            for (int h = 0; h < 2; h++) {
                int j = wi*16 + la + 8*h;
                float s = 0.f;
                #pragma unroll
                for (int n = 0; n < 4; n++)
                    #pragma unroll
                    for (int p = 0; p < 2; p++) {
                        int ch = wj*32 + n*8 + 2*lb + p;
                        s = fmaf(sacc[n][2*h+p], __uint_as_float(Bstf[j*68 + ch]), s);
                    }
                s += __shfl_xor_sync(0xffffffffu, s, 1);
                s += __shfl_xor_sync(0xffffffffu, s, 2);
                if (lb == 0) zred[j*5 + wj] = s;
            }
        }
        if (t < 64) {
            float m = 0.f;
            #pragma unroll 8
            for (int c = 0; c < 64; c++)
                m = fmaf(__uint_as_float(Bstf[t*68 + c]),
                         __uint_as_float(Gm[c*68 + 64]), m);
            zred[t*5 + 4] = m;
        }
        __syncthreads();
        if (t < 64) {
            float var = (zred[t*5] + zred[t*5+1]) * (1.f/511.f);
            float sc = LOG2E / (5.f * sqrtf(var + GN_EPS));
            bscale[t] = sc;
            bofs[t]   = zred[t*5+4] * sc;
        }
        __syncthreads();

        float cs[8], co[8];
        #pragma unroll
        for (int n = 0; n < 4; n++)
            #pragma unroll
            for (int p = 0; p < 2; p++) {
                int col = wj*32 + n*8 + 2*lb + p;
                cs[2*n+p] = bscale[col];
                co[2*n+p] = bofs[col];
            }

        float zp[8];
        #pragma unroll
        for (int i = 0; i < 8; i++) zp[i] = 0.f;

        /* prefetch A block 0 */
        float4 pf[4];
        #pragma unroll
        for (int j = 0; j < 4; j++)
            pf[j] = *(const float4*)(A + (size_t)(srow + j*16)*CP + scol);

        for (int ab = 0; ab < 8; ab++) {
            __syncthreads();   /* prior GEMM done with Astf */
            #pragma unroll
            for (int j = 0; j < 4; j++) {
                float4 v = pf[j];
                *(uint4*)(Astf + (srow + j*16)*68 + scol) =
                    make_uint4(to_tf32(v.x), to_tf32(v.y), to_tf32(v.z), to_tf32(v.w));
            }
            if (ab < 7) {
                #pragma unroll
                for (int j = 0; j < 4; j++)
                    pf[j] = *(const float4*)(A + (size_t)((ab+1)*64 + srow + j*16)*CP + scol);
            }
            __syncthreads();

            float acc[4][4];
            #pragma unroll
            for (int n = 0; n < 4; n++)
                #pragma unroll
                for (int e = 0; e < 4; e++) acc[n][e] = 0.f;

            #pragma unroll
            for (int ks = 0; ks < 8; ks++) {
                int k0 = ks*8 + 2*lb;
                uint2 a0 = *(uint2*)(Astf + (wi*16 + la)*68 + k0);
                uint2 a1 = *(uint2*)(Astf + (wi*16 + la + 8)*68 + k0);
                uint2 bf[4];
                #pragma unroll
                for (int n = 0; n < 4; n++)
                    bf[n] = *(uint2*)(Bstf + (wj*32 + n*8 + la)*68 + k0);
                #pragma unroll
                for (int n = 0; n < 4; n++)
                    mma_tf32(acc[n], a0.x, a1.x, a0.y, a1.y, bf[n].x, bf[n].y);
            }

            /* exp -> Ebuf fp16; Z partials stay in regs across ab */
            #pragma unroll
            for (int h = 0; h < 2; h++) {
                int arow = ab*64 + wi*16 + la + 8*h;
                __half* erow = Ebuf + arow*70 + wj*32;
                #pragma unroll
                for (int n = 0; n < 4; n++) {
                    float e0 = ex2(fmaf(acc[n][2*h+0], cs[2*n+0], -co[2*n+0]));
                    float e1 = ex2(fmaf(acc[n][2*h+1], cs[2*n+1], -co[2*n+1]));
                    zp[2*n+0] += e0;
                    zp[2*n+1] += e1;
                    *(__half2*)(erow + n*8 + 2*lb) = __floats2half2_rn(e0, e1);
                }
            }
        }

        /* Z reduction: over la lanes (shfl), then over wi warps (smem) */
        #pragma unroll
        for (int i = 0; i < 8; i++) {
            float v = zp[i];
            v += __shfl_xor_sync(0xffffffffu, v, 4);
            v += __shfl_xor_sync(0xffffffffu, v, 8);
            v += __shfl_xor_sync(0xffffffffu, v, 16);
            zp[i] = v;
        }
        if (la == 0) {
            #pragma unroll
            for (int n = 0; n < 4; n++)
                #pragma unroll
                for (int p = 0; p < 2; p++) {
                    int col = wj*32 + n*8 + 2*lb + p;
                    zred[col*5 + wi] = zp[2*n+p];
                }
        }
        __syncthreads();
        if (t < 64) {
            float z = zred[t*5] + zred[t*5+1] + zred[t*5+2] + zred[t*5+3];
            zsum[t] = 1.f / z;
        }
        __syncthreads();

        /* attn accumulation: conflict-free (stride 35 words, odd) */
        {
            const __half* r0p = Ebuf + t*70;
            const __half* r1p = Ebuf + (t+256)*70;
            #pragma unroll 8
            for (int c = 0; c < 64; c += 2) {
                float2 f0 = __half22float2(*(const __half2*)(r0p + c));
                float2 f1 = __half22float2(*(const __half2*)(r1p + c));
                float rz0 = zsum[c], rz1 = zsum[c+1];
                attn0 = fmaf(f0.x, rz0, fmaf(f0.y, rz1, attn0));
                attn1 = fmaf(f1.x, rz0, fmaf(f1.y, rz1, attn1));
            }
        }
    }
    outp[t] = attn0;
    outp[t + 256] = attn1;
}

/* ------------- K3: attention-weighted pooling + cosine sim ------------- */
__global__ __launch_bounds__(256) void kfinal(const float* __restrict__ sup,
                                              const float* __restrict__ qry,
                                              float* __restrict__ out) {
    __shared__ float as_[512], aq_[512], ms[512], mq[512];
    __shared__ float ps[CIN], pq[CIN];
    __shared__ float rbuf[256];

    int pair = blockIdx.x;
    int q = pair / WAY, w = pair % WAY;
    int t = threadIdx.x, warp = t >> 5, lane = t & 31;

    for (int j = t; j < 512; j += 256) {
        as_[j] = g_as[pair*NTOK + j];
        aq_[j] = g_aq[pair*NTOK + j];
        ms[j]  = g_mS[w*NTOK + j];
        mq[j]  = g_mQ[q*NTOK + j];
    }
    __syncthreads();

    const float* xs = sup + (size_t)w*CIN*NTOK;
    const float* xq = qry + (size_t)q*CIN*NTOK;

    for (int c = warp; c < CIN; c += 8) {
        float v = 0.f, v2 = 0.f;
        #pragma unroll 4
        for (int i = lane; i < 512; i += 32) {
            v  += as_[i] * (xs[(size_t)c*NTOK + i] - ms[i]);
            v2 += aq_[i] * (xq[(size_t)c*NTOK + i] - mq[i]);
        }
        v  = warp_sum(v);
        v2 = warp_sum(v2);
        if (lane == 0) { ps[c] = v; pq[c] = v2; }
    }
    __syncthreads();

    float dp = 0.f, ns = 0.f, nq2 = 0.f;
    for (int c = t; c < CIN; c += 256) {
        float a = ps[c], b = pq[c];
        dp += a*b; ns += a*a; nq2 += b*b;
    }
    float vals[3] = {dp, ns, nq2};
    float red3[3];
    for (int r = 0; r < 3; r++) {
        rbuf[t] = vals[r];
        __syncthreads();
        for (int s = 128; s > 0; s >>= 1) {
            if (t < s) rbuf[t] += rbuf[t + s];
            __syncthreads();
        }
        red3[r] = rbuf[0];
        __syncthreads();
    }
    if (t == 0) {
        float psn = fmaxf(sqrtf(red3[1]) * (1.f/512.f), L2_EPS);
        float pqn = fmaxf(sqrtf(red3[2]) * (1.f/512.f), L2_EPS);
        float sim = (red3[0] * (1.f/(512.f*512.f))) / (psn * pqn);
        out[pair] = sim * 5.f;
    }
}

/* ------------- launcher ------------- */
extern "C" void kernel_launch(void* const* d_in, const int* in_sizes, int n_in,
                              void* d_out, int out_size) {
    const float* sup   = (const float*)d_in[0];
    const float* qry   = (const float*)d_in[1];
    const float* W     = (const float*)d_in[2];
    const float* gamma = (const float*)d_in[3];
    const float* beta  = (const float*)d_in[4];
    const float* mean  = (const float*)d_in[5];
    const float* var   = (const float*)d_in[6];
    float* out = (float*)d_out;

    cudaFuncSetAttribute(kpass, cudaFuncAttributeMaxDynamicSharedMemorySize, KP_SMEM_BYTES);

    kpre<<<1, 256>>>(W, gamma, beta, mean, var);
    kproj<<<(WAY+NQ)*4, 256>>>(sup, qry, W);
    kgram<<<WAY+NQ, 256>>>();
    kpass<<<2*PAIRS, 256, KP_SMEM_BYTES>>>();
    kfinal<<<PAIRS, 256>>>(sup, qry, out);
}

// round 8
// speedup vs baseline: 1.3123x; 1.3123x over previous
#include <cuda_runtime.h>
#include <cuda_fp16.h>
#include <cuda_bf16.h>

#define WAY   5
#define NQ    75
#define CIN   640
#define NTOK  512
#define CP    64
#define PAIRS (WAY*NQ)          /* 375 */
#define BN_EPS 1e-5f
#define GN_EPS 1e-5f
#define L2_EPS 1e-8f
#define LOG2E  1.4426950408889634f

/* scratch (device globals)
 * g_S/g_Q: [batch][tok 512][ch 64], channels PERMUTED by perm8() */
__device__ float g_S[WAY*NTOK*CP];
__device__ float g_Q[NQ*NTOK*CP];
__device__ float g_mS[WAY*NTOK];
__device__ float g_mQ[NQ*NTOK];
__device__ float g_G[(WAY+NQ)*CP*CP];
__device__ float g_bar[(WAY+NQ)*CP];
__device__ float g_as[PAIRS*NTOK];
__device__ float g_aq[PAIRS*NTOK];
__device__ float g_ps[PAIRS*CIN];        // raw pooled support (pre mean-correction)
__device__ float g_pq[PAIRS*CIN];        // raw pooled query
__device__ float g_wsum[CP];
__device__ float g_scale[CP];
__device__ float g_bias[CP];

__device__ __forceinline__ float ex2(float x) {
    float y;
    asm("ex2.approx.ftz.f32 %0, %1;" : "=f"(y) : "f"(x));
    return y;
}
__device__ __forceinline__ float warp_sum(float v) {
    #pragma unroll
    for (int o = 16; o; o >>= 1) v += __shfl_xor_sync(0xffffffffu, v, o);
    return v;
}
__device__ __forceinline__ unsigned to_tf32(float f) {
    unsigned u;
    asm("cvt.rna.tf32.f32 %0, %1;" : "=r"(u) : "f"(f));
    return u;
}
__device__ __forceinline__ int perm8(int c) {
    return (c & ~7) | ((c & 3) * 2) | ((c >> 2) & 1);
}
__device__ __forceinline__ void mma_tf32(float* d, unsigned a0, unsigned a1,
                                         unsigned a2, unsigned a3,
                                         unsigned b0, unsigned b1) {
    asm volatile(
        "mma.sync.aligned.m16n8k8.row.col.f32.tf32.tf32.f32 "
        "{%0,%1,%2,%3}, {%4,%5,%6,%7}, {%8,%9}, {%0,%1,%2,%3};"
        : "+f"(d[0]), "+f"(d[1]), "+f"(d[2]), "+f"(d[3])
        : "r"(a0), "r"(a1), "r"(a2), "r"(a3), "r"(b0), "r"(b1));
}

/* ------------- K-pre: BN fold + weight row sums (parallel) ------------- */
__global__ void kpre(const float* __restrict__ W, const float* __restrict__ gamma,
                     const float* __restrict__ beta, const float* __restrict__ mean,
                     const float* __restrict__ var) {
    int t = threadIdx.x;
    int o = t >> 2, ln = t & 3;
    float s = 0.f;
    for (int c = ln; c < CIN; c += 4) s += W[o*CIN + c];
    s += __shfl_xor_sync(0xffffffffu, s, 1);
    s += __shfl_xor_sync(0xffffffffu, s, 2);
    if (ln == 0) {
        g_wsum[o] = s;
        float sc = gamma[o] * rsqrtf(var[o] + BN_EPS);
        g_scale[o] = sc;
        g_bias[o]  = beta[o] - mean[o] * sc;
    }
}

/* ------------- K0: projection, writes transposed+permuted [tok][64] ------------- */
__global__ __launch_bounds__(256) void kproj(const float* __restrict__ sup,
                                             const float* __restrict__ qry,
                                             const float* __restrict__ W) {
    __shared__ float pool[128*68];
    __shared__ float minv[128];
    __shared__ float linv[128];
    float* ws = pool;                  // [32][65]
    float* xs = pool + 32*65;          // [32][128]

    int b  = blockIdx.x >> 2;
    int n0 = (blockIdx.x & 3) * 128;
    const float* x  = (b < WAY) ? sup + (size_t)b*CIN*NTOK : qry + (size_t)(b-WAY)*CIN*NTOK;
    float* outp     = (b < WAY) ? g_S + b*NTOK*CP          : g_Q + (b-WAY)*NTOK*CP;
    float* moutp    = (b < WAY) ? g_mS + b*NTOK            : g_mQ + (b-WAY)*NTOK;

    int t  = threadIdx.x;
    int tx = t & 15, ty = t >> 4;

    float acc[4][8];
    #pragma unroll
    for (int u = 0; u < 4; u++)
        #pragma unroll
        for (int v = 0; v < 8; v++) acc[u][v] = 0.f;
    float cs = 0.f;

    for (int cc = 0; cc < CIN; cc += 32) {
        for (int j = t; j < 32*64; j += 256) {
            int o = j >> 5, cr = j & 31;
            ws[cr*65 + o] = W[o*CIN + cc + cr];
        }
        for (int j = t; j < 32*128; j += 256) {
            int r = j >> 7, col = j & 127;
            xs[r*128 + col] = x[(size_t)(cc + r)*NTOK + n0 + col];
        }
        __syncthreads();
        if (t < 128) {
            #pragma unroll 8
            for (int r = 0; r < 32; r++) cs += xs[r*128 + t];
        }
        #pragma unroll 4
        for (int kc = 0; kc < 32; kc++) {
            float a[4], bb[8];
            #pragma unroll
            for (int u = 0; u < 4; u++) a[u] = ws[kc*65 + ty*4 + u];
            #pragma unroll
            for (int v = 0; v < 8; v++) bb[v] = xs[kc*128 + tx*8 + v];
            #pragma unroll
            for (int u = 0; u < 4; u++)
                #pragma unroll
                for (int v = 0; v < 8; v++)
                    acc[u][v] = fmaf(a[u], bb[v], acc[u][v]);
        }
        __syncthreads();
    }
    if (t < 128) minv[t] = cs * (1.f/CIN);
    __syncthreads();

    float* psum = pool;
    float ssq[8];
    #pragma unroll
    for (int v = 0; v < 8; v++) ssq[v] = 0.f;
    #pragma unroll
    for (int u = 0; u < 4; u++) {
        int o = ty*4 + u;
        float wsm = g_wsum[o], sc = g_scale[o], bi = g_bias[o];
        #pragma unroll
        for (int v = 0; v < 8; v++) {
            float y = acc[u][v] - wsm * minv[tx*8 + v];
            y = fmaxf(y * sc + bi, 0.f);
            acc[u][v] = y;
            ssq[v] += y * y;
        }
    }
    #pragma unroll
    for (int v = 0; v < 8; v++) psum[ty*128 + tx*8 + v] = ssq[v];
    __syncthreads();
    if (t < 128) {
        float s = 0.f;
        #pragma unroll
        for (int r = 0; r < 16; r++) s += psum[r*128 + t];
        linv[t] = 1.f / fmaxf(sqrtf(s), L2_EPS);
        moutp[n0 + t] = minv[t];
    }
    __syncthreads();

    float* stg = pool;                 // [128][68]
    #pragma unroll
    for (int u = 0; u < 4; u++) {
        int p = perm8(ty*4 + u);
        #pragma unroll
        for (int v = 0; v < 8; v++) {
            int col = tx*8 + v;
            stg[col*68 + p] = acc[u][v] * linv[col];
        }
    }
    __syncthreads();
    for (int idx = t; idx < 128*16; idx += 256) {
        int col = idx >> 4, c4 = (idx & 15) << 2;
        float4 val = *(float4*)&stg[col*68 + c4];
        *(float4*)(outp + (size_t)(n0 + col)*CP + c4) = val;
    }
}

/* ------------- Kgram: per batch token-mean + centered Gram (64x64) ------------- */
__global__ __launch_bounds__(256) void kgram() {
    __shared__ float Xs[128*68];
    __shared__ float abar_s[64];

    int b = blockIdx.x;
    const float* X = (b < WAY) ? g_S + (size_t)b*NTOK*CP
                               : g_Q + (size_t)(b-WAY)*NTOK*CP;
    int t = threadIdx.x;

    float csum = 0.f;
    for (int ck = 0; ck < 4; ck++) {
        for (int idx = t; idx < 128*16; idx += 256) {
            int r = idx >> 4, c4 = (idx & 15) << 2;
            *(float4*)&Xs[r*68 + c4] = *(const float4*)(X + (size_t)(ck*128 + r)*CP + c4);
        }
        __syncthreads();
        if (t < 64) {
            #pragma unroll 8
            for (int r = 0; r < 128; r++) csum += Xs[r*68 + t];
        }
        __syncthreads();
    }
    if (t < 64) {
        float m = csum * (1.f/512.f);
        abar_s[t] = m;
        g_bar[b*CP + t] = m;
    }
    __syncthreads();

    float gacc[4][4];
    #pragma unroll
    for (int i = 0; i < 4; i++)
        #pragma unroll
        for (int j = 0; j < 4; j++) gacc[i][j] = 0.f;
    int a0 = (t >> 4) * 4, b0 = (t & 15) * 4;

    for (int ck = 0; ck < 4; ck++) {
        for (int idx = t; idx < 128*16; idx += 256) {
            int r = idx >> 4, c4 = (idx & 15) << 2;
            float4 v = *(const float4*)(X + (size_t)(ck*128 + r)*CP + c4);
            v.x -= abar_s[c4+0]; v.y -= abar_s[c4+1];
            v.z -= abar_s[c4+2]; v.w -= abar_s[c4+3];
            *(float4*)&Xs[r*68 + c4] = v;
        }
        __syncthreads();
        #pragma unroll 4
        for (int r = 0; r < 128; r++) {
            float4 av = *(float4*)&Xs[r*68 + a0];
            float4 bv = *(float4*)&Xs[r*68 + b0];
            float aa[4] = {av.x, av.y, av.z, av.w};
            float bb[4] = {bv.x, bv.y, bv.z, bv.w};
            #pragma unroll
            for (int i = 0; i < 4; i++)
                #pragma unroll
                for (int j = 0; j < 4; j++)
                    gacc[i][j] = fmaf(aa[i], bb[j], gacc[i][j]);
        }
        __syncthreads();
    }
    #pragma unroll
    for (int i = 0; i < 4; i++)
        #pragma unroll
        for (int j = 0; j < 4; j++)
            g_G[(size_t)b*CP*CP + (a0+i)*CP + b0+j] = gacc[i][j];
}

/* ------------- Kpass: fused storeless GEMM + gaussian-softmax + attn sums -------------
 * (round-6 tiling: 128-col stripes, 231KB smem, 1 CTA/SM — measured best)
 */
#define KP_SMEM_BYTES 231168

extern "C" __global__ void __launch_bounds__(256, 1) kpass() {
    extern __shared__ unsigned char kp_sm[];
    unsigned* Bstf = (unsigned*)kp_sm;            // [128][68] tf32
    unsigned* Astf = Bstf + 128*68;               // [128][68]
    unsigned* Gm   = Astf + 128*68;               // [64][68]
    __half*  Ebuf  = (__half*)(Gm + 64*68);       // [512][136]
    float* zred    = (float*)(Ebuf + 512*136);    // [128][5]
    float* bscale  = zred + 128*5;                // [128]
    float* bofs    = bscale + 128;
    float* bmean   = bofs + 128;
    float* zsum    = bmean + 128;
    float* abar    = zsum + 128;                  // [64]

    int bid = blockIdx.x;
    int mode = (bid >= PAIRS);
    int pair = bid - mode*PAIRS;
    int qq = pair / WAY, ww = pair % WAY;
    const float *A, *B, *Gp, *barp;
    float* outp;
    if (mode == 0) {
        A = g_S + (size_t)ww*NTOK*CP;  B = g_Q + (size_t)qq*NTOK*CP;
        Gp = g_G + (size_t)ww*CP*CP;   barp = g_bar + ww*CP;
        outp = g_as + pair*NTOK;
    } else {
        A = g_Q + (size_t)qq*NTOK*CP;  B = g_S + (size_t)ww*NTOK*CP;
        Gp = g_G + (size_t)(WAY+qq)*CP*CP;  barp = g_bar + (WAY+qq)*CP;
        outp = g_aq + pair*NTOK;
    }

    int t = threadIdx.x, lane = t & 31, warp = t >> 5;
    int wi = warp >> 1, wj = warp & 1;
    int la = lane >> 2, lb = lane & 3;

    for (int i = t; i < 64*64; i += 256)
        Gm[(i >> 6)*68 + (i & 63)] = to_tf32(Gp[i]);
    if (t < 64) abar[t] = barp[t];

    float attn0 = 0.f, attn1 = 0.f;

    for (int sb = 0; sb < 4; sb++) {
        __syncthreads();
        for (int idx = t; idx < 128*16; idx += 256) {
            int r = idx >> 4, c4 = (idx & 15) << 2;
            float4 v = *(const float4*)(B + (size_t)(sb*128 + r)*CP + c4);
            uint4 u = make_uint4(to_tf32(v.x), to_tf32(v.y), to_tf32(v.z), to_tf32(v.w));
            *(uint4*)(Bstf + r*68 + c4) = u;
        }
        if (t < 128) zsum[t] = 0.f;
        __syncthreads();

        /* stats: H = Bstf*G', 511*var_j = b_j.h_j */
        {
            float sacc[2][4][4];
            #pragma unroll
            for (int m = 0; m < 2; m++)
                #pragma unroll
                for (int n = 0; n < 4; n++)
                    #pragma unroll
                    for (int e = 0; e < 4; e++) sacc[m][n][e] = 0.f;
            #pragma unroll
            for (int ks = 0; ks < 8; ks++) {
                int k0 = ks*8 + 2*lb;
                uint2 saf[2][2];
                #pragma unroll
                for (int m = 0; m < 2; m++) {
                    int r0 = wi*32 + m*16 + la;
                    saf[m][0] = *(uint2*)(Bstf + r0*68 + k0);
                    saf[m][1] = *(uint2*)(Bstf + (r0+8)*68 + k0);
                }
                uint2 sbf[4];
                #pragma unroll
                for (int n = 0; n < 4; n++) {
                    int j0 = wj*32 + n*8 + la;
                    sbf[n] = *(uint2*)(Gm + j0*68 + k0);
                }
                #pragma unroll
                for (int m = 0; m < 2; m++)
                    #pragma unroll
                    for (int n = 0; n < 4; n++)
                        mma_tf32(sacc[m][n], saf[m][0].x, saf[m][1].x,
                                 saf[m][0].y, saf[m][1].y, sbf[n].x, sbf[n].y);
            }
            #pragma unroll
            for (int m = 0; m < 2; m++)
                #pragma unroll
                for (int h = 0; h < 2; h++) {
                    int j = wi*32 + m*16 + la + 8*h;
                    float s = 0.f;
                    #pragma unroll
                    for (int n = 0; n < 4; n++)
                        #pragma unroll
                        for (int p = 0; p < 2; p++) {
                            int ch = wj*32 + n*8 + 2*lb + p;
                            s = fmaf(sacc[m][n][2*h+p],
                                     __uint_as_float(Bstf[j*68 + ch]), s);
                        }
                    s += __shfl_xor_sync(0xffffffffu, s, 1);
                    s += __shfl_xor_sync(0xffffffffu, s, 2);
                    if (lb == 0) zred[j*5 + wj] = s;
                }
        }
        if (t < 128) {
            float m = 0.f;
            #pragma unroll 8
            for (int c = 0; c < 64; c++)
                m = fmaf(__uint_as_float(Bstf[t*68 + c]), abar[c], m);
            bmean[t] = m;
        }
        __syncthreads();
        if (t < 128) {
            float var = (zred[t*5] + zred[t*5+1]) * (1.f/511.f);
            float sc = LOG2E / (5.f * sqrtf(var + GN_EPS));
            bscale[t] = sc;
            bofs[t] = bmean[t] * sc;
        }
        __syncthreads();

        float cs[16], co[16];
        #pragma unroll
        for (int n = 0; n < 8; n++)
            #pragma unroll
            for (int p = 0; p < 2; p++) {
                int col = wj*64 + n*8 + 2*lb + p;
                cs[2*n+p] = bscale[col];
                co[2*n+p] = bofs[col];
            }

        for (int ab = 0; ab < 4; ab++) {
            __syncthreads();
            for (int idx = t; idx < 128*16; idx += 256) {
                int r = idx >> 4, c4 = (idx & 15) << 2;
                float4 v = *(const float4*)(A + (size_t)(ab*128 + r)*CP + c4);
                uint4 u = make_uint4(to_tf32(v.x), to_tf32(v.y), to_tf32(v.z), to_tf32(v.w));
                *(uint4*)(Astf + r*68 + c4) = u;
            }
            __syncthreads();

            float acc[2][8][4];
            #pragma unroll
            for (int m = 0; m < 2; m++)
                #pragma unroll
                for (int n = 0; n < 8; n++)
                    #pragma unroll
                    for (int e = 0; e < 4; e++) acc[m][n][e] = 0.f;

            #pragma unroll
            for (int ks = 0; ks < 8; ks++) {
                int k0 = ks*8 + 2*lb;
                uint2 af[2][2];
                #pragma unroll
                for (int m = 0; m < 2; m++) {
                    int r0 = wi*32 + m*16 + la;
                    af[m][0] = *(uint2*)(Astf + r0*68 + k0);
                    af[m][1] = *(uint2*)(Astf + (r0+8)*68 + k0);
                }
                uint2 bf[8];
                #pragma unroll
                for (int n = 0; n < 8; n++) {
                    int j0 = wj*64 + n*8 + la;
                    bf[n] = *(uint2*)(Bstf + j0*68 + k0);
                }
                #pragma unroll
                for (int m = 0; m < 2; m++)
                    #pragma unroll
                    for (int n = 0; n < 8; n++)
                        mma_tf32(acc[m][n], af[m][0].x, af[m][1].x,
                                 af[m][0].y, af[m][1].y, bf[n].x, bf[n].y);
            }

            float zp[16];
            #pragma unroll
            for (int i = 0; i < 16; i++) zp[i] = 0.f;
            #pragma unroll
            for (int m = 0; m < 2; m++)
                #pragma unroll
                for (int h = 0; h < 2; h++) {
                    int arow = ab*128 + wi*32 + m*16 + la + 8*h;
                    __half* erow = Ebuf + arow*136 + wj*64;
                    #pragma unroll
                    for (int n = 0; n < 8; n++) {
                        float e0 = ex2(fmaf(acc[m][n][2*h+0], cs[2*n+0], -co[2*n+0]));
                        float e1 = ex2(fmaf(acc[m][n][2*h+1], cs[2*n+1], -co[2*n+1]));
                        zp[2*n+0] += e0;
                        zp[2*n+1] += e1;
                        *(__half2*)(erow + n*8 + 2*lb) = __floats2half2_rn(e0, e1);
                    }
                }
            #pragma unroll
            for (int n = 0; n < 8; n++)
                #pragma unroll
                for (int p = 0; p < 2; p++) {
                    float v = zp[2*n+p];
                    v += __shfl_xor_sync(0xffffffffu, v, 4);
                    v += __shfl_xor_sync(0xffffffffu, v, 8);
                    v += __shfl_xor_sync(0xffffffffu, v, 16);
                    if (la == 0)
                        zred[(wj*64 + n*8 + 2*lb + p)*5 + wi] = v;
                }
            __syncthreads();
            if (t < 128)
                zsum[t] += zred[t*5] + zred[t*5+1] + zred[t*5+2] + zred[t*5+3];
        }
        __syncthreads();
        if (t < 128) zsum[t] = 1.f / zsum[t];
        __syncthreads();

        {
            const __half* r0p = Ebuf + t*136;
            const __half* r1p = Ebuf + (t+256)*136;
            #pragma unroll 4
            for (int jj = 0; jj < 16; jj++) {
                uint4 e0 = *(const uint4*)(r0p + jj*8);
                uint4 e1 = *(const uint4*)(r1p + jj*8);
                const __half2* h0 = (const __half2*)&e0;
                const __half2* h1 = (const __half2*)&e1;
                #pragma unroll
                for (int u = 0; u < 4; u++) {
                    float2 f0 = __half22float2(h0[u]);
                    float2 f1 = __half22float2(h1[u]);
                    int c = jj*8 + u*2;
                    float rz0 = zsum[c], rz1 = zsum[c+1];
                    attn0 = fmaf(f0.x, rz0, attn0);
                    attn0 = fmaf(f0.y, rz1, attn0);
                    attn1 = fmaf(f1.x, rz0, attn1);
                    attn1 = fmaf(f1.y, rz1, attn1);
                }
            }
        }
    }
    outp[t] = attn0;
    outp[t + 256] = attn1;
}

/* ------------- KpoolS: pooled_s raw = attn_s x sup[w] (sup read once) -------------
 * grid = 5 w x 10 ch-tiles. Per CTA: [75 q][64 ch] outputs, K=512 in 128-chunks.
 */
#define PS_SMEM ((64*129 + 75*128) * 4)   /* 71424 B */

__global__ __launch_bounds__(256) void kpoolS(const float* __restrict__ sup) {
    extern __shared__ float ps_sm[];
    float* xs  = ps_sm;              // [64][129]
    float* asb = ps_sm + 64*129;     // [75][128]

    int w = blockIdx.x / 10, ct = blockIdx.x % 10;
    int c0 = ct*64;
    int t = threadIdx.x;
    int c = t & 63, qb = t >> 6;
    const float* X = sup + (size_t)w*CIN*NTOK + (size_t)c0*NTOK;

    float acc[19];
    #pragma unroll
    for (int j = 0; j < 19; j++) acc[j] = 0.f;

    for (int i0 = 0; i0 < NTOK; i0 += 128) {
        __syncthreads();
        for (int idx = t; idx < 64*32; idx += 256) {
            int r = idx >> 5, i4 = (idx & 31) << 2;
            float4 v = *(const float4*)(X + (size_t)r*NTOK + i0 + i4);
            xs[r*129 + i4+0] = v.x; xs[r*129 + i4+1] = v.y;
            xs[r*129 + i4+2] = v.z; xs[r*129 + i4+3] = v.w;
        }
        for (int idx = t; idx < 75*32; idx += 256) {
            int r = idx / 32, i4 = (idx & 31) << 2;
            *(float4*)&asb[r*128 + i4] =
                *(const float4*)(g_as + (size_t)(r*WAY + w)*NTOK + i0 + i4);
        }
        __syncthreads();
        for (int i = 0; i < 128; i += 4) {
            float x0 = xs[c*129 + i],   x1 = xs[c*129 + i+1];
            float x2 = xs[c*129 + i+2], x3 = xs[c*129 + i+3];
            #pragma unroll
            for (int j = 0; j < 19; j++) {
                int q = qb + 4*j;
                if (q < NQ) {
                    float4 a = *(float4*)&asb[q*128 + i];
                    acc[j] = fmaf(a.x, x0, fmaf(a.y, x1, fmaf(a.z, x2, fmaf(a.w, x3, acc[j]))));
                }
            }
        }
    }
    #pragma unroll
    for (int j = 0; j < 19; j++) {
        int q = qb + 4*j;
        if (q < NQ) g_ps[(size_t)(q*WAY + w)*CIN + c0 + c] = acc[j];
    }
}

/* ------------- KpoolQ: pooled_q raw = attn_q x qry[q] (qry read once) -------------
 * grid = 75 q x 10 ch-tiles. Per CTA: [5 w][64 ch], 4 thread-groups split i-range.
 */
__global__ __launch_bounds__(256) void kpoolQ(const float* __restrict__ qry) {
    __shared__ float xs[64*129];     // 33024 B
    __shared__ float aqb[5*128];
    __shared__ float red[5*64*4];

    int q = blockIdx.x / 10, ct = blockIdx.x % 10;
    int c0 = ct*64;
    int t = threadIdx.x;
    int c = t & 63, g = t >> 6;
    const float* X = qry + (size_t)q*CIN*NTOK + (size_t)c0*NTOK;

    float acc[5] = {0.f, 0.f, 0.f, 0.f, 0.f};

    for (int i0 = 0; i0 < NTOK; i0 += 128) {
        __syncthreads();
        for (int idx = t; idx < 64*32; idx += 256) {
            int r = idx >> 5, i4 = (idx & 31) << 2;
            float4 v = *(const float4*)(X + (size_t)r*NTOK + i0 + i4);
            xs[r*129 + i4+0] = v.x; xs[r*129 + i4+1] = v.y;
            xs[r*129 + i4+2] = v.z; xs[r*129 + i4+3] = v.w;
        }
        for (int idx = t; idx < 5*32; idx += 256) {
            int r = idx / 32, i4 = (idx & 31) << 2;
            *(float4*)&aqb[r*128 + i4] =
                *(const float4*)(g_aq + (size_t)(q*WAY + r)*NTOK + i0 + i4);
        }
        __syncthreads();
        for (int i = g*32; i < g*32 + 32; i += 4) {
            float x0 = xs[c*129 + i],   x1 = xs[c*129 + i+1];
            float x2 = xs[c*129 + i+2], x3 = xs[c*129 + i+3];
            #pragma unroll
            for (int wv = 0; wv < 5; wv++) {
                float4 a = *(float4*)&aqb[wv*128 + i];
                acc[wv] = fmaf(a.x, x0, fmaf(a.y, x1, fmaf(a.z, x2, fmaf(a.w, x3, acc[wv]))));
            }
        }
    }
    #pragma unroll
    for (int wv = 0; wv < 5; wv++) red[(wv*64 + c)*4 + g] = acc[wv];
    __syncthreads();
    for (int idx = t; idx < 5*64; idx += 256) {
        int wv = idx >> 6, cc = idx & 63;
        float s = red[idx*4] + red[idx*4+1] + red[idx*4+2] + red[idx*4+3];
        g_pq[(size_t)(q*WAY + wv)*CIN + c0 + cc] = s;
    }
}

/* ------------- Kcos: mean corrections + cosine sim ------------- */
__global__ __launch_bounds__(128) void kcos(float* __restrict__ out) {
    __shared__ float rbuf[4*5];
    int pair = blockIdx.x, q = pair / WAY, w = pair % WAY;
    int t = threadIdx.x, lane = t & 31, wp = t >> 5;

    float cS = 0.f, cQ = 0.f;
    for (int i = t; i < NTOK; i += 128) {
        cS = fmaf(g_as[pair*NTOK + i], g_mS[w*NTOK + i], cS);
        cQ = fmaf(g_aq[pair*NTOK + i], g_mQ[q*NTOK + i], cQ);
    }
    cS = warp_sum(cS); cQ = warp_sum(cQ);
    if (lane == 0) { rbuf[wp*5+0] = cS; rbuf[wp*5+1] = cQ; }
    __syncthreads();
    cS = rbuf[0] + rbuf[5] + rbuf[10] + rbuf[15];
    cQ = rbuf[1] + rbuf[6] + rbuf[11] + rbuf[16];
    __syncthreads();

    float dp = 0.f, ns = 0.f, nq2 = 0.f;
    for (int c = t; c < CIN; c += 128) {
        float a = g_ps[(size_t)pair*CIN + c] - cS;
        float b = g_pq[(size_t)pair*CIN + c] - cQ;
        dp = fmaf(a, b, dp); ns = fmaf(a, a, ns); nq2 = fmaf(b, b, nq2);
    }
    dp = warp_sum(dp); ns = warp_sum(ns); nq2 = warp_sum(nq2);
    if (lane == 0) { rbuf[wp*5+0] = dp; rbuf[wp*5+1] = ns; rbuf[wp*5+2] = nq2; }
    __syncthreads();
    if (t == 0) {
        dp  = rbuf[0] + rbuf[5] + rbuf[10] + rbuf[15];
        ns  = rbuf[1] + rbuf[6] + rbuf[11] + rbuf[16];
        nq2 = rbuf[2] + rbuf[7] + rbuf[12] + rbuf[17];
        float psn = fmaxf(sqrtf(ns)  * (1.f/512.f), L2_EPS);
        float pqn = fmaxf(sqrtf(nq2) * (1.f/512.f), L2_EPS);
        out[pair] = (dp * (1.f/(512.f*512.f))) / (psn * pqn) * 5.f;
    }
}

/* ------------- launcher ------------- */
extern "C" void kernel_launch(void* const* d_in, const int* in_sizes, int n_in,
                              void* d_out, int out_size) {
    const float* sup   = (const float*)d_in[0];
    const float* qry   = (const float*)d_in[1];
    const float* W     = (const float*)d_in[2];
    const float* gamma = (const float*)d_in[3];
    const float* beta  = (const float*)d_in[4];
    const float* mean  = (const float*)d_in[5];
    const float* var   = (const float*)d_in[6];
    float* out = (float*)d_out;

    cudaFuncSetAttribute(kpass, cudaFuncAttributeMaxDynamicSharedMemorySize, KP_SMEM_BYTES);
    cudaFuncSetAttribute(kpoolS, cudaFuncAttributeMaxDynamicSharedMemorySize, PS_SMEM);

    kpre<<<1, 256>>>(W, gamma, beta, mean, var);
    kproj<<<(WAY+NQ)*4, 256>>>(sup, qry, W);
    kgram<<<WAY+NQ, 256>>>();
    kpass<<<2*PAIRS, 256, KP_SMEM_BYTES>>>();
    kpoolS<<<WAY*10, 256, PS_SMEM>>>(sup);
    kpoolQ<<<NQ*10, 256>>>(qry);
    kcos<<<PAIRS, 128>>>(out);
}